// round 11
// baseline (speedup 1.0000x reference)
#include <cuda_runtime.h>
#include <cstdint>
#include <cstddef>

// Problem constants
#define S_LEN 4096
#define D 2048
#define DV 512            // D / 4 (float4 columns)
#define NT 32000
#define NTV 8000          // NT / 4
#define INP 4097          // D + D + 1
#define N_NODES 4097      // S_LEN + 1
#define NP 256            // partial chunks for colsum / lmv stages
#define NBLK 296          // 2 blocks/SM on 148 SMs (co-resident by launch_bounds)
#define NTHR (NBLK * 256)
#define NWARP (NTHR / 32)
#define KC 64             // k-chunks for output matvec (32 rows each)

// ---------------- scratch (device globals; no allocation) ----------------
__device__ float g_bufA[NP * D];        // partial ping (2 MB)
__device__ float g_bufB[NP * D];        // partial pong (2 MB)
__device__ float g_inp[INP];            // only [D, 2D) = graph_emb used
__device__ float g_gxp[2 * 4 * D];      // half-row gate dots: [half][row]
__device__ float g_pout[KC * NT];       // output matvec partials (8 MB)
__device__ unsigned g_hbits[D / 32];    // per-warp ballots of cur_h != 0
__device__ unsigned g_hflag;            // OR of g_hbits (rewritten every launch)
__device__ unsigned g_bar_cnt;          // zero-init; always returns to 0
__device__ volatile unsigned g_bar_gen; // monotonically increasing generation

// ---------------- grid-wide barrier (all NBLK blocks co-resident) --------
__device__ __forceinline__ void grid_bar() {
    __syncthreads();
    if (threadIdx.x == 0) {
        unsigned gen = g_bar_gen;
        __threadfence();                       // publish this block's phase writes
        if (atomicAdd(&g_bar_cnt, 1u) == NBLK - 1u) {
            g_bar_cnt = 0u;
            __threadfence();                   // reset visible before release
            g_bar_gen = gen + 1u;
        } else {
            while (g_bar_gen == gen) { __nanosleep(64); }
        }
    }
    __syncthreads();
}

__device__ __forceinline__ float sigf(float x) { return 1.f / (1.f + expf(-x)); }

// Fused matvec stage over 512 virtual tiles (256 k-chunks x 2 column halves).
__device__ void lmv_stage(const float* __restrict__ partin,
                          const float4* __restrict__ W4,
                          float* __restrict__ partout,
                          const float* __restrict__ addvec,
                          float scale, int do_relu,
                          float* red, float* vsh) {
    int t = threadIdx.x;
    for (int vt = blockIdx.x; vt < 512; vt += NBLK) {
        int ky = vt >> 1;
        int k0 = ky * 8;
        int c4 = (vt & 1) * 256 + t;
        // prefetch W rows (independent of prologue)
        float4 w[8];
        #pragma unroll
        for (int j = 0; j < 8; ++j)
            w[j] = W4[(size_t)(k0 + j) * DV + c4];
        // prologue: reduce partin over NP chunks for columns k0..k0+7
        {
            int c  = k0 + (t & 7);
            int p0 = t >> 3;                   // 0..31
            float acc = 0.f;
            #pragma unroll
            for (int i = 0; i < 8; ++i)
                acc += partin[(p0 + i * 32) * D + c];
            __syncthreads();                   // guard red reuse across tiles
            red[t] = acc;
        }
        __syncthreads();
        #pragma unroll
        for (int s = 128; s >= 8; s >>= 1) {
            if (t < s) red[t] += red[t + s];
            __syncthreads();
        }
        if (t < 8) {
            float v = red[t];
            if (addvec) v += addvec[k0 + t];
            v *= scale;
            if (do_relu) v = fmaxf(v, 0.f);
            vsh[t] = v;
        }
        __syncthreads();
        float4 a = make_float4(0.f, 0.f, 0.f, 0.f);
        #pragma unroll
        for (int j = 0; j < 8; ++j) {
            float s_ = vsh[j];
            a.x += s_ * w[j].x; a.y += s_ * w[j].y;
            a.z += s_ * w[j].z; a.w += s_ * w[j].w;
        }
        ((float4*)partout)[ky * DV + c4] = a;
    }
}

// ---------------- the whole network in one persistent kernel -------------
__global__ void __launch_bounds__(256, 2) k_mega(
        const float* __restrict__ sen, const int* __restrict__ pos_raw,
        const float4* __restrict__ hid4,
        const float4* __restrict__ dim_up4, const float4* __restrict__ W_gcn4,
        const float4* __restrict__ dim_down4, const float4* __restrict__ dim_out4,
        const float* __restrict__ Wi, const float4* __restrict__ Wh4,
        const float* __restrict__ bi, const float* __restrict__ bh,
        const float* __restrict__ cur_h, const float* __restrict__ cur_cell,
        float* __restrict__ out) {
    __shared__ float red[256];
    __shared__ float vsh[128];
    int t = threadIdx.x;
    int g = blockIdx.x * 256 + t;
    int wg = g >> 5, lane = t & 31;

    // pos value, dtype-defensive (int bits vs float bits)
    int pbits = pos_raw[0];
    float posv = (pbits >= 0 && pbits < 1000000) ? (float)pbits
                                                 : __int_as_float(pbits);

    // ---- P0: ballot cur_h, colsum partials -> bufA ----
    if (g < D) {
        unsigned b = __ballot_sync(0xffffffffu, cur_h[g] != 0.f);
        if (lane == 0) g_hbits[wg] = b;        // always overwritten: deterministic
    }
    for (int item = g; item < NP * DV; item += NTHR) {
        int chunk = item >> 9, c4 = item & 511;
        float4 w[16];
        #pragma unroll
        for (int r = 0; r < 16; ++r)
            w[r] = hid4[(size_t)(chunk * 16 + r) * DV + c4];
        float4 a = make_float4(0.f, 0.f, 0.f, 0.f);
        #pragma unroll
        for (int r = 0; r < 16; ++r) {
            a.x += w[r].x; a.y += w[r].y; a.z += w[r].z; a.w += w[r].w;
        }
        ((float4*)g_bufA)[item] = a;           // item == chunk*DV + c4
    }
    grid_bar();

    // ---- P1..P3: graph chain ----
    lmv_stage(g_bufA, dim_up4,   g_bufB, nullptr, 1.0f, 0, red, vsh);
    grid_bar();
    lmv_stage(g_bufB, W_gcn4,    g_bufA, cur_h, 1.0f / (float)N_NODES, 0, red, vsh);
    grid_bar();
    lmv_stage(g_bufA, dim_down4, g_bufB, nullptr, 1.0f, 1, red, vsh);
    grid_bar();

    // ---- P4: final reduce of dim_down partials -> g_inp[D : 2D); flag OR ----
    if (g == 0) {
        unsigned f = 0;
        #pragma unroll
        for (int i = 0; i < D / 32; ++i) f |= g_hbits[i];
        g_hflag = f;                           // always overwritten: deterministic
    }
    for (int c = wg; c < D; c += NWARP) {
        float a = 0.f;
        #pragma unroll
        for (int i = 0; i < 8; ++i)
            a += g_bufB[(lane + i * 32) * D + c];
        #pragma unroll
        for (int o = 16; o; o >>= 1) a += __shfl_down_sync(0xffffffffu, a, o);
        if (lane == 0) g_inp[D + c] = a;
    }
    grid_bar();

    // ---- P5: gate dots, half-row items (16384 items, ~6.9/warp) ----
    // item (row, 0): dot(Wi_row[0:2048], sen) + Wi_row[4096]*pos
    // item (row, 1): dot(Wi_row[2048:4096], graph_emb) [+ Wh_row . cur_h if nonzero]
    {
        unsigned hnz = g_hflag;
        for (int it = wg; it < 2 * 4 * D; it += NWARP) {
            int row  = it >> 1;
            int half = it & 1;
            float acc = 0.f;
            if (half == 0) {
                const float* p = Wi + (size_t)row * INP;
                #pragma unroll
                for (int b = 0; b < 4; ++b) {
                    float w[16];
                    int base = b * 512 + lane;
                    #pragma unroll
                    for (int j = 0; j < 16; ++j) w[j] = __ldg(p + base + j * 32);
                    #pragma unroll
                    for (int j = 0; j < 16; ++j) acc += w[j] * __ldg(sen + base + j * 32);
                }
                if (lane == 0) acc += p[4096] * posv;
            } else {
                const float* p = Wi + (size_t)row * INP + D;
                #pragma unroll
                for (int b = 0; b < 4; ++b) {
                    float w[16];
                    int base = b * 512 + lane;
                    #pragma unroll
                    for (int j = 0; j < 16; ++j) w[j] = __ldg(p + base + j * 32);
                    #pragma unroll
                    for (int j = 0; j < 16; ++j) acc += w[j] * g_inp[D + base + j * 32];
                }
                if (hnz) {
                    const float4* wh_row = Wh4 + (size_t)row * DV;
                    const float4* curh4  = (const float4*)cur_h;
                    #pragma unroll
                    for (int b = 0; b < 2; ++b) {
                        float4 w[8];
                        int base = b * 256 + lane;
                        #pragma unroll
                        for (int j = 0; j < 8; ++j) w[j] = __ldg(wh_row + base + j * 32);
                        #pragma unroll
                        for (int j = 0; j < 8; ++j) {
                            float4 h = __ldg(curh4 + base + j * 32);
                            acc += w[j].x * h.x + w[j].y * h.y + w[j].z * h.z + w[j].w * h.w;
                        }
                    }
                }
            }
            #pragma unroll
            for (int o = 16; o; o >>= 1) acc += __shfl_down_sync(0xffffffffu, acc, o);
            if (lane == 0) g_gxp[half * 4 * D + row] = acc;
        }
    }
    grid_bar();

    // ---- P6: output matvec partials, 2048 tiles (32 k-rows x 1024 cols) ----
    for (int vt = blockIdx.x; vt < KC * 32; vt += NBLK) {
        int kc = vt >> 5, nb = vt & 31;
        int k0 = kc * 32;
        __syncthreads();                       // guard vsh reuse across tiles
        if (t < 32) {
            int k = k0 + t;
            const float* gx0 = g_gxp;
            const float* gx1 = g_gxp + 4 * D;
            float gi = gx0[k]         + gx1[k]         + bi[k]         + bh[k];
            float gf = gx0[D + k]     + gx1[D + k]     + bi[D + k]     + bh[D + k];
            float gg = gx0[2 * D + k] + gx1[2 * D + k] + bi[2 * D + k] + bh[2 * D + k];
            float go = gx0[3 * D + k] + gx1[3 * D + k] + bi[3 * D + k] + bh[3 * D + k];
            float nc = sigf(gf) * cur_cell[k] + sigf(gi) * tanhf(gg);
            vsh[t] = sigf(go) * tanhf(nc);
        }
        __syncthreads();
        int n4 = nb * 256 + t;
        if (n4 < NTV) {
            float4 a = make_float4(0.f, 0.f, 0.f, 0.f);
            #pragma unroll
            for (int kb = 0; kb < 32; kb += 16) {
                float4 w[16];
                #pragma unroll
                for (int j = 0; j < 16; ++j)
                    w[j] = dim_out4[(size_t)(k0 + kb + j) * NTV + n4];
                #pragma unroll
                for (int j = 0; j < 16; ++j) {
                    float h = vsh[kb + j];
                    a.x += h * w[j].x; a.y += h * w[j].y;
                    a.z += h * w[j].z; a.w += h * w[j].w;
                }
            }
            ((float4*)g_pout)[kc * NTV + n4] = a;
        }
    }
    grid_bar();

    // ---- P7: output reduce over KC partials ----
    for (int n4 = g; n4 < NTV; n4 += NTHR) {
        float4 a = make_float4(0.f, 0.f, 0.f, 0.f);
        #pragma unroll 8
        for (int k = 0; k < KC; ++k) {
            float4 v = ((const float4*)g_pout)[k * NTV + n4];
            a.x += v.x; a.y += v.y; a.z += v.z; a.w += v.w;
        }
        ((float4*)out)[n4] = a;
    }
}

// ---------------- launcher ----------------
// Inputs: 0 sen_emb [D], 1 hiddens [S,D], 2 pos_index [1], 3 dim_up [D,D],
// 4 dim_down [D,D], 5 dim_out [D,NT], 6 W_gcn [D,D], 7 att_w (unused; softmax
// over identical rows is exactly uniform), 8 Wi [4,D,INP], 9 Wh [4,D,D],
// 10 bi, 11 bh, 12 cur_h [D], 13 cur_cell [D]
extern "C" void kernel_launch(void* const* d_in, const int* in_sizes, int n_in,
                              void* d_out, int out_size) {
    const float* sen_emb  = (const float*)d_in[0];
    const float* hiddens  = (const float*)d_in[1];
    const int*   pos_raw  = (const int*)  d_in[2];
    const float* dim_up   = (const float*)d_in[3];
    const float* dim_down = (const float*)d_in[4];
    const float* dim_out  = (const float*)d_in[5];
    const float* W_gcn    = (const float*)d_in[6];
    const float* Wi       = (const float*)d_in[8];
    const float* Wh       = (const float*)d_in[9];
    const float* bi       = (const float*)d_in[10];
    const float* bh       = (const float*)d_in[11];
    const float* cur_h    = (const float*)d_in[12];
    const float* cur_cell = (const float*)d_in[13];
    float* out = (float*)d_out;

    k_mega<<<NBLK, 256>>>(
        sen_emb, pos_raw,
        (const float4*)hiddens,
        (const float4*)dim_up, (const float4*)W_gcn,
        (const float4*)dim_down, (const float4*)dim_out,
        Wi, (const float4*)Wh, bi, bh,
        cur_h, cur_cell, out);
}

// round 13
// speedup vs baseline: 1.0488x; 1.0488x over previous
#include <cuda_runtime.h>
#include <cstdint>
#include <cstddef>

// Problem constants
#define S_LEN 4096
#define D 2048
#define DV 512            // D / 4 (float4 columns)
#define NT 32000
#define NTV 8000          // NT / 4
#define INP 4097          // D + D + 1
#define N_NODES 4097      // S_LEN + 1
#define NP 256            // partial chunks for colsum / lmv stages
#define NBLK 296          // 2 blocks/SM on 148 SMs (co-resident by launch_bounds)
#define NTHR (NBLK * 256)
#define NWARP (NTHR / 32)

// ---------------- scratch (device globals; no allocation) ----------------
__device__ float g_bufA[NP * D];        // partial ping (2 MB)
__device__ float g_bufB[NP * D];        // partial pong (2 MB)
__device__ float g_inp[INP];            // LSTM input vector
__device__ float g_gsum[4 * D];         // gate pre-activations
__device__ float g_pout[16 * NT];       // output matvec partials (2 MB)
__device__ unsigned g_hbits[D / 32];    // per-warp ballots of cur_h != 0
__device__ unsigned g_hflag;            // OR of g_hbits (rewritten every launch)
__device__ unsigned g_tk[8];            // per-phase ticket counters (reset in P7)
__device__ unsigned g_bar_cnt;          // zero-init; always returns to 0
__device__ volatile unsigned g_bar_gen; // monotonically increasing generation

// ---------------- grid-wide barrier (all NBLK blocks co-resident) --------
__device__ __forceinline__ void grid_bar() {
    __syncthreads();
    if (threadIdx.x == 0) {
        unsigned gen = g_bar_gen;
        __threadfence();                       // publish this block's phase writes
        if (atomicAdd(&g_bar_cnt, 1u) == NBLK - 1u) {
            g_bar_cnt = 0u;
            __threadfence();                   // reset visible before release
            g_bar_gen = gen + 1u;
        } else {
            while (g_bar_gen == gen) { }
        }
    }
    __syncthreads();
}

__device__ __forceinline__ float sigf(float x) { return 1.f / (1.f + expf(-x)); }

// Fused matvec stage over 512 tiles (256 k-chunks x 2 column halves),
// dynamically scheduled via ticket counter (perfect load balance).
__device__ void lmv_stage(const float* __restrict__ partin,
                          const float4* __restrict__ W4,
                          float* __restrict__ partout,
                          const float* __restrict__ addvec,
                          float scale, int do_relu,
                          float* red, float* vsh, unsigned* tk_sh,
                          unsigned* ctr) {
    int t = threadIdx.x;
    for (;;) {
        __syncthreads();                       // tk_sh / red / vsh reuse guard
        if (t == 0) *tk_sh = atomicAdd(ctr, 1u);
        __syncthreads();
        unsigned vt = *tk_sh;
        if (vt >= 512u) break;
        int ky = vt >> 1;
        int k0 = ky * 8;
        int c4 = (vt & 1) * 256 + t;
        // prefetch W rows (independent of prologue)
        float4 w[8];
        #pragma unroll
        for (int j = 0; j < 8; ++j)
            w[j] = W4[(size_t)(k0 + j) * DV + c4];
        // prologue: reduce partin over NP chunks for columns k0..k0+7
        {
            int c  = k0 + (t & 7);
            int p0 = t >> 3;                   // 0..31
            float acc = 0.f;
            #pragma unroll
            for (int i = 0; i < 8; ++i)
                acc += partin[(p0 + i * 32) * D + c];
            red[t] = acc;
        }
        __syncthreads();
        #pragma unroll
        for (int s = 128; s >= 8; s >>= 1) {
            if (t < s) red[t] += red[t + s];
            __syncthreads();
        }
        if (t < 8) {
            float v = red[t];
            if (addvec) v += addvec[k0 + t];
            v *= scale;
            if (do_relu) v = fmaxf(v, 0.f);
            vsh[t] = v;
        }
        __syncthreads();
        float4 a = make_float4(0.f, 0.f, 0.f, 0.f);
        #pragma unroll
        for (int j = 0; j < 8; ++j) {
            float s_ = vsh[j];
            a.x += s_ * w[j].x; a.y += s_ * w[j].y;
            a.z += s_ * w[j].z; a.w += s_ * w[j].w;
        }
        ((float4*)partout)[ky * DV + c4] = a;
    }
}

// ---------------- the whole network in one persistent kernel -------------
__global__ void __launch_bounds__(256, 2) k_mega(
        const float* __restrict__ sen, const int* __restrict__ pos_raw,
        const float4* __restrict__ hid4,
        const float4* __restrict__ dim_up4, const float4* __restrict__ W_gcn4,
        const float4* __restrict__ dim_down4, const float4* __restrict__ dim_out4,
        const float* __restrict__ Wi, const float4* __restrict__ Wh4,
        const float* __restrict__ bi, const float* __restrict__ bh,
        const float* __restrict__ cur_h, const float* __restrict__ cur_cell,
        float* __restrict__ out) {
    __shared__ float red[256];
    __shared__ float vsh[128];
    __shared__ unsigned tk_sh;
    int t = threadIdx.x;
    int g = blockIdx.x * 256 + t;
    int wg = g >> 5, lane = t & 31;

    // ---- P0: prep g_inp, ballot cur_h nonzeros, colsum partials -> bufA ----
    if (g < D) {
        g_inp[g] = sen[g];                     // sen_emb half of LSTM input
        unsigned b = __ballot_sync(0xffffffffu, cur_h[g] != 0.f);
        if (lane == 0) g_hbits[wg] = b;        // always overwritten: deterministic
    }
    if (g == D) {
        int bits = pos_raw[0];
        g_inp[2 * D] = (bits >= 0 && bits < 1000000) ? (float)bits
                                                     : __int_as_float(bits);
    }
    for (int item = g; item < NP * DV; item += NTHR) {
        int chunk = item >> 9, c4 = item & 511;
        float4 w[16];
        #pragma unroll
        for (int r = 0; r < 16; ++r)
            w[r] = hid4[(size_t)(chunk * 16 + r) * DV + c4];
        float4 a = make_float4(0.f, 0.f, 0.f, 0.f);
        #pragma unroll
        for (int r = 0; r < 16; ++r) {
            a.x += w[r].x; a.y += w[r].y; a.z += w[r].z; a.w += w[r].w;
        }
        ((float4*)g_bufA)[item] = a;           // item == chunk*DV + c4
    }
    grid_bar();

    // ---- P1..P3: graph chain (ticket-scheduled) ----
    lmv_stage(g_bufA, dim_up4,   g_bufB, nullptr, 1.0f, 0, red, vsh, &tk_sh, &g_tk[0]);
    grid_bar();
    lmv_stage(g_bufB, W_gcn4,    g_bufA, cur_h, 1.0f / (float)N_NODES, 0, red, vsh, &tk_sh, &g_tk[1]);
    grid_bar();
    lmv_stage(g_bufA, dim_down4, g_bufB, nullptr, 1.0f, 1, red, vsh, &tk_sh, &g_tk[2]);
    grid_bar();

    // ---- P4: final reduce of dim_down partials -> g_inp[D : 2D); flag OR ----
    if (g == 0) {
        unsigned f = 0;
        #pragma unroll
        for (int i = 0; i < D / 32; ++i) f |= g_hbits[i];
        g_hflag = f;                           // always overwritten: deterministic
    }
    for (int c = wg; c < D; c += NWARP) {
        float a = 0.f;
        #pragma unroll
        for (int i = 0; i < 8; ++i)
            a += g_bufB[(lane + i * 32) * D + c];
        #pragma unroll
        for (int o = 16; o; o >>= 1) a += __shfl_down_sync(0xffffffffu, a, o);
        if (lane == 0) g_inp[D + c] = a;
    }
    grid_bar();

    // ---- P5: LSTM gate pre-activations, ticket-scheduled 8-row items ----
    // Wh stream skipped when cur_h is identically zero (runtime-guarded).
    {
        unsigned hnz = g_hflag;
        int wid = t >> 5;
        for (;;) {
            __syncthreads();
            if (t == 0) tk_sh = atomicAdd(&g_tk[3], 1u);
            __syncthreads();
            unsigned it = tk_sh;
            if (it >= 1024u) break;            // 1024 items x 8 rows = 8192 rows
            int row = (int)it * 8 + wid;
            const float* wi_row = Wi + (size_t)row * INP;
            float acc = 0.f;
            #pragma unroll
            for (int b = 0; b < 8; ++b) {
                float w[16];
                int base = b * 512 + lane;
                #pragma unroll
                for (int j = 0; j < 16; ++j) w[j] = __ldg(wi_row + base + j * 32);
                #pragma unroll
                for (int j = 0; j < 16; ++j) acc += w[j] * g_inp[base + j * 32];
            }
            if (lane == 0) acc += wi_row[4096] * g_inp[4096];
            if (hnz) {
                const float4* wh_row = Wh4 + (size_t)row * DV;
                const float4* curh4  = (const float4*)cur_h;
                #pragma unroll
                for (int b = 0; b < 2; ++b) {
                    float4 w[8];
                    int base = b * 256 + lane;
                    #pragma unroll
                    for (int j = 0; j < 8; ++j) w[j] = __ldg(wh_row + base + j * 32);
                    #pragma unroll
                    for (int j = 0; j < 8; ++j) {
                        float4 h = __ldg(curh4 + base + j * 32);
                        acc += w[j].x * h.x + w[j].y * h.y + w[j].z * h.z + w[j].w * h.w;
                    }
                }
            }
            #pragma unroll
            for (int o = 16; o; o >>= 1) acc += __shfl_down_sync(0xffffffffu, acc, o);
            if (lane == 0) g_gsum[row] = acc + bi[row] + bh[row];
        }
    }
    grid_bar();

    // ---- P6: output matvec partials with fused gates (ticket-scheduled) ----
    for (;;) {
        __syncthreads();                       // vsh / tk_sh reuse guard
        if (t == 0) tk_sh = atomicAdd(&g_tk[4], 1u);
        __syncthreads();
        unsigned vt = tk_sh;
        if (vt >= 512u) break;
        int kc = vt >> 5, nb = vt & 31;
        int k0 = kc * 128;
        if (t < 128) {
            int k = k0 + t;
            float i_g = sigf(g_gsum[k]);
            float f_g = sigf(g_gsum[D + k]);
            float g_g = tanhf(g_gsum[2 * D + k]);
            float o_g = sigf(g_gsum[3 * D + k]);
            float nc  = f_g * cur_cell[k] + i_g * g_g;
            vsh[t] = o_g * tanhf(nc);
        }
        __syncthreads();
        int n4 = nb * 256 + t;
        if (n4 < NTV) {
            float4 a = make_float4(0.f, 0.f, 0.f, 0.f);
            #pragma unroll 1
            for (int kb = 0; kb < 128; kb += 16) {
                float4 w[16];
                #pragma unroll
                for (int j = 0; j < 16; ++j)
                    w[j] = dim_out4[(size_t)(k0 + kb + j) * NTV + n4];
                #pragma unroll
                for (int j = 0; j < 16; ++j) {
                    float h = vsh[kb + j];
                    a.x += h * w[j].x; a.y += h * w[j].y;
                    a.z += h * w[j].z; a.w += h * w[j].w;
                }
            }
            ((float4*)g_pout)[kc * NTV + n4] = a;
        }
    }
    grid_bar();

    // ---- P7: output reduce; reset ticket counters for next graph replay ----
    if (g == 0) {
        #pragma unroll
        for (int i = 0; i < 8; ++i) g_tk[i] = 0u;   // all grabbing done at bar
    }
    for (int n4 = g; n4 < NTV; n4 += NTHR) {
        float4 a = make_float4(0.f, 0.f, 0.f, 0.f);
        #pragma unroll
        for (int k = 0; k < 16; ++k) {
            float4 v = ((const float4*)g_pout)[k * NTV + n4];
            a.x += v.x; a.y += v.y; a.z += v.z; a.w += v.w;
        }
        ((float4*)out)[n4] = a;
    }
}

// ---------------- launcher ----------------
// Inputs: 0 sen_emb [D], 1 hiddens [S,D], 2 pos_index [1], 3 dim_up [D,D],
// 4 dim_down [D,D], 5 dim_out [D,NT], 6 W_gcn [D,D], 7 att_w (unused; softmax
// over identical rows is exactly uniform), 8 Wi [4,D,INP], 9 Wh [4,D,D],
// 10 bi, 11 bh, 12 cur_h [D], 13 cur_cell [D]
extern "C" void kernel_launch(void* const* d_in, const int* in_sizes, int n_in,
                              void* d_out, int out_size) {
    const float* sen_emb  = (const float*)d_in[0];
    const float* hiddens  = (const float*)d_in[1];
    const int*   pos_raw  = (const int*)  d_in[2];
    const float* dim_up   = (const float*)d_in[3];
    const float* dim_down = (const float*)d_in[4];
    const float* dim_out  = (const float*)d_in[5];
    const float* W_gcn    = (const float*)d_in[6];
    const float* Wi       = (const float*)d_in[8];
    const float* Wh       = (const float*)d_in[9];
    const float* bi       = (const float*)d_in[10];
    const float* bh       = (const float*)d_in[11];
    const float* cur_h    = (const float*)d_in[12];
    const float* cur_cell = (const float*)d_in[13];
    float* out = (float*)d_out;

    k_mega<<<NBLK, 256>>>(
        sen_emb, pos_raw,
        (const float4*)hiddens,
        (const float4*)dim_up, (const float4*)W_gcn,
        (const float4*)dim_down, (const float4*)dim_out,
        Wi, (const float4*)Wh, bi, bh,
        cur_h, cur_cell, out);
}